// round 1
// baseline (speedup 1.0000x reference)
#include <cuda_runtime.h>
#include <cuda_bf16.h>

// GraphDenoiser: N=768, F=256, H=128
// Pipeline:
//  1) dinv[i] = rsqrt(1 + rowsum(adj[i,:]))
//  2) anorm[i,j] = dinv[i]*dinv[j]*(adj[i,j] + (i==j))
//  3) xw  = x @ w1                      (768x256 @ 256x128)
//  4) h1  = relu(anorm @ xw)            (768x768 @ 768x128)
//  5) hw  = h1 @ w2                     (768x128 @ 128x128)
//  6) h2  = relu(anorm @ hw)            (768x768 @ 768x128)
//  7) p   = h2 @ we1[0:128,:]           (768x128 @ 128x128)
//     q   = h2 @ we1[128:256,:]
//  8) c[h]= sum_k time_emb[t,k]*we1[256+k,h] + be1[h]
//  9) sig[i,j] = sigmoid( sum_h relu(p[i,h]+q[j,h]+c[h]) * we2[h] + be2 )
// 10) out[i,j] = 0.5*(sig[i,j]+sig[j,i])

#define NN   768
#define FDIM 256
#define HH   128

// ------------------- scratch (device globals, no allocs) -------------------
__device__ float g_dinv[NN];
__device__ float g_anorm[NN * NN];
__device__ float g_xw[NN * HH];
__device__ float g_h1[NN * HH];
__device__ float g_hw[NN * HH];
__device__ float g_h2[NN * HH];
__device__ float g_p[NN * HH];
__device__ float g_q[NN * HH];
__device__ float g_c[HH];
__device__ float g_sig[NN * NN];

// ------------------- 1) degree inverse sqrt -------------------
__global__ void dinv_kernel(const float* __restrict__ adj, float* __restrict__ dinv) {
    int row  = blockIdx.x * 8 + (threadIdx.x >> 5);
    int lane = threadIdx.x & 31;
    const float* r = adj + row * NN;
    float s = 0.f;
    #pragma unroll 6
    for (int j = lane; j < NN; j += 32) s += r[j];
    #pragma unroll
    for (int o = 16; o; o >>= 1) s += __shfl_xor_sync(0xffffffffu, s, o);
    s += 1.0f;  // self loop
    if (lane == 0) dinv[row] = (s > 0.f) ? rsqrtf(s) : 0.f;
}

// ------------------- 2) normalized adjacency -------------------
__global__ void anorm_kernel(const float* __restrict__ adj,
                             const float* __restrict__ dinv,
                             float* __restrict__ anorm) {
    int idx = blockIdx.x * 256 + threadIdx.x;   // 768*768 / 256 = 2304 blocks
    int i = idx / NN, j = idx - i * NN;
    float v = adj[idx] + (i == j ? 1.0f : 0.0f);
    anorm[idx] = dinv[i] * dinv[j] * v;
}

// ------------------- generic fp32 GEMM: C = op(A@B), 64x64 tile -------------------
// BM=BN=64, BK=16, 256 threads, 4x4 micro-tile. M%64==0, N%64==0, K%16==0 assumed.
template <bool RELU>
__global__ void gemm64_kernel(const float* __restrict__ A, const float* __restrict__ B,
                              float* __restrict__ C, int M, int N, int K) {
    __shared__ float As[16][65];
    __shared__ float Bs[16][65];
    const int row0 = blockIdx.y * 64;
    const int col0 = blockIdx.x * 64;
    const int tid = threadIdx.x;
    const int ty = tid >> 4, tx = tid & 15;

    float acc[4][4] = {};
    for (int k0 = 0; k0 < K; k0 += 16) {
        #pragma unroll
        for (int l = tid; l < 64 * 16; l += 256) {
            int r = l >> 4, c = l & 15;
            As[c][r] = A[(row0 + r) * K + k0 + c];
        }
        #pragma unroll
        for (int l = tid; l < 16 * 64; l += 256) {
            int r = l >> 6, c = l & 63;
            Bs[r][c] = B[(k0 + r) * N + col0 + c];
        }
        __syncthreads();
        #pragma unroll
        for (int k = 0; k < 16; k++) {
            float a[4], b[4];
            #pragma unroll
            for (int m = 0; m < 4; m++) a[m] = As[k][ty * 4 + m];
            #pragma unroll
            for (int n = 0; n < 4; n++) b[n] = Bs[k][tx * 4 + n];
            #pragma unroll
            for (int m = 0; m < 4; m++)
                #pragma unroll
                for (int n = 0; n < 4; n++)
                    acc[m][n] = fmaf(a[m], b[n], acc[m][n]);
        }
        __syncthreads();
    }
    #pragma unroll
    for (int m = 0; m < 4; m++) {
        int gr = row0 + ty * 4 + m;
        #pragma unroll
        for (int n = 0; n < 4; n++) {
            float v = acc[m][n];
            if (RELU) v = fmaxf(v, 0.0f);
            C[gr * N + col0 + tx * 4 + n] = v;
        }
    }
}

// ------------------- 8) time-embedding contribution c -------------------
__global__ void c_kernel(const float* __restrict__ time_emb, const int* __restrict__ t_ptr,
                         const float* __restrict__ we1, const float* __restrict__ be1,
                         float* __restrict__ cvec) {
    int h = threadIdx.x;  // 128
    int t = t_ptr[0];
    const float* te = time_emb + t * HH;
    float s = be1[h];
    #pragma unroll 8
    for (int k = 0; k < HH; k++)
        s = fmaf(te[k], we1[(2 * HH + k) * HH + h], s);
    cvec[h] = s;
}

// ------------------- 9) edge MLP + sigmoid -------------------
// tile 64x64 outputs, h chunked by 32, 256 threads, 4x4 micro-tile.
__global__ void edge_kernel(const float* __restrict__ p, const float* __restrict__ q,
                            const float* __restrict__ cvec, const float* __restrict__ we2,
                            const float* __restrict__ be2, float* __restrict__ sig) {
    __shared__ float Ps[32][65];
    __shared__ float Qs[32][65];
    __shared__ float Ws[32];
    const int i0 = blockIdx.y * 64;
    const int j0 = blockIdx.x * 64;
    const int tid = threadIdx.x;
    const int ty = tid >> 4, tx = tid & 15;

    float acc[4][4] = {};
    #pragma unroll
    for (int h0 = 0; h0 < HH; h0 += 32) {
        #pragma unroll
        for (int l = tid; l < 64 * 32; l += 256) {
            int r = l >> 5, c = l & 31;     // r: row in tile, c: h offset
            Ps[c][r] = p[(i0 + r) * HH + h0 + c];
            Qs[c][r] = q[(j0 + r) * HH + h0 + c] + cvec[h0 + c];
        }
        if (tid < 32) Ws[tid] = we2[h0 + tid];
        __syncthreads();
        #pragma unroll
        for (int k = 0; k < 32; k++) {
            float w = Ws[k];
            float pv[4], qv[4];
            #pragma unroll
            for (int m = 0; m < 4; m++) pv[m] = Ps[k][ty * 4 + m];
            #pragma unroll
            for (int n = 0; n < 4; n++) qv[n] = Qs[k][tx * 4 + n];
            #pragma unroll
            for (int m = 0; m < 4; m++)
                #pragma unroll
                for (int n = 0; n < 4; n++) {
                    float v = pv[m] + qv[n];
                    acc[m][n] = fmaf(fmaxf(v, 0.0f), w, acc[m][n]);
                }
        }
        __syncthreads();
    }
    float b = be2[0];
    #pragma unroll
    for (int m = 0; m < 4; m++) {
        int gi = i0 + ty * 4 + m;
        #pragma unroll
        for (int n = 0; n < 4; n++) {
            int gj = j0 + tx * 4 + n;
            float logit = acc[m][n] + b;
            sig[gi * NN + gj] = 1.0f / (1.0f + __expf(-logit));
        }
    }
}

// ------------------- 10) symmetrize -------------------
__global__ void sym_kernel(const float* __restrict__ sig, float* __restrict__ out) {
    int idx = blockIdx.x * 256 + threadIdx.x;
    int i = idx / NN, j = idx - i * NN;
    out[idx] = 0.5f * (sig[idx] + sig[j * NN + i]);
}

// ------------------- launch -------------------
extern "C" void kernel_launch(void* const* d_in, const int* in_sizes, int n_in,
                              void* d_out, int out_size) {
    const float* x        = (const float*)d_in[0];   // 768x256
    const float* adj      = (const float*)d_in[1];   // 768x768
    const float* w1       = (const float*)d_in[2];   // 256x128
    const float* w2       = (const float*)d_in[3];   // 128x128
    const float* time_emb = (const float*)d_in[4];   // 100x128
    const float* we1      = (const float*)d_in[5];   // 384x128
    const float* be1      = (const float*)d_in[6];   // 128
    const float* we2      = (const float*)d_in[7];   // 128x1
    const float* be2      = (const float*)d_in[8];   // 1
    const int*   t_ptr    = (const int*)d_in[9];     // scalar
    float* out = (float*)d_out;

    float *dinv, *anorm, *xw, *h1, *hw, *h2, *pp, *qq, *cv, *sg;
    cudaGetSymbolAddress((void**)&dinv,  g_dinv);
    cudaGetSymbolAddress((void**)&anorm, g_anorm);
    cudaGetSymbolAddress((void**)&xw,    g_xw);
    cudaGetSymbolAddress((void**)&h1,    g_h1);
    cudaGetSymbolAddress((void**)&hw,    g_hw);
    cudaGetSymbolAddress((void**)&h2,    g_h2);
    cudaGetSymbolAddress((void**)&pp,    g_p);
    cudaGetSymbolAddress((void**)&qq,    g_q);
    cudaGetSymbolAddress((void**)&cv,    g_c);
    cudaGetSymbolAddress((void**)&sg,    g_sig);

    dinv_kernel<<<NN / 8, 256>>>(adj, dinv);
    anorm_kernel<<<NN * NN / 256, 256>>>(adj, dinv, anorm);

    // xw = x @ w1
    gemm64_kernel<false><<<dim3(HH / 64, NN / 64), 256>>>(x, w1, xw, NN, HH, FDIM);
    // h1 = relu(anorm @ xw)
    gemm64_kernel<true><<<dim3(HH / 64, NN / 64), 256>>>(anorm, xw, h1, NN, HH, NN);
    // hw = h1 @ w2
    gemm64_kernel<false><<<dim3(HH / 64, NN / 64), 256>>>(h1, w2, hw, NN, HH, HH);
    // h2 = relu(anorm @ hw)
    gemm64_kernel<true><<<dim3(HH / 64, NN / 64), 256>>>(anorm, hw, h2, NN, HH, NN);
    // p, q
    gemm64_kernel<false><<<dim3(HH / 64, NN / 64), 256>>>(h2, we1, pp, NN, HH, HH);
    gemm64_kernel<false><<<dim3(HH / 64, NN / 64), 256>>>(h2, we1 + HH * HH, qq, NN, HH, HH);

    c_kernel<<<1, HH>>>(time_emb, t_ptr, we1, be1, cv);

    edge_kernel<<<dim3(NN / 64, NN / 64), 256>>>(pp, qq, cv, we2, be2, sg);
    sym_kernel<<<NN * NN / 256, 256>>>(sg, out);
}

// round 2
// speedup vs baseline: 4.2640x; 4.2640x over previous
#include <cuda_runtime.h>
#include <cuda_bf16.h>

// GraphDenoiser: N=768, F=256, H=128
// Fused-normalization split-K formulation:
//  dinv[i] = rsqrt(1 + rowsum(adj))
//  A@B with A = D^-1/2 (adj+I) D^-1/2 computed as: dinv_i * sum_k (adj+I)[i,k] * (dinv_k * B[k,:])
//  h1 = relu(Anorm @ (x@w1)); h2 = relu(Anorm @ (h1@w2))
//  pq = h2 @ [we1_p | we1_q]  (packed N=256)
//  c  = t_emb @ we1[2H:] + be1
//  sig = sigmoid(sum_h relu(p_i + q_j + c) * we2 + be2); out = (sig + sig^T)/2

#define NN   768
#define FDIM 256
#define HH   128

// ------------------- scratch -------------------
__device__ __align__(16) float g_dinv[NN];
__device__ __align__(16) float g_xw[NN * HH];
__device__ __align__(16) float g_h1[NN * HH];
__device__ __align__(16) float g_hw[NN * HH];
__device__ __align__(16) float g_h2[NN * HH];
__device__ __align__(16) float g_pq[NN * 2 * HH];
__device__ __align__(16) float g_bpack[HH * 2 * HH];
__device__ __align__(16) float g_c[HH];
__device__ __align__(16) float g_sig[NN * NN];
__device__ __align__(16) float g_part[6 * NN * HH];   // max(6*768*128, 2*768*256)

// ------------------- degree inverse sqrt -------------------
__global__ void dinv_kernel(const float* __restrict__ adj, float* __restrict__ dinv) {
    int row  = blockIdx.x * 8 + (threadIdx.x >> 5);
    int lane = threadIdx.x & 31;
    const float4* r = (const float4*)(adj + row * NN);
    float s = 0.f;
    #pragma unroll
    for (int j = lane; j < NN / 4; j += 32) {
        float4 v = r[j];
        s += (v.x + v.y) + (v.z + v.w);
    }
    #pragma unroll
    for (int o = 16; o; o >>= 1) s += __shfl_xor_sync(0xffffffffu, s, o);
    s += 1.0f;  // self loop
    if (lane == 0) dinv[row] = (s > 0.f) ? rsqrtf(s) : 0.f;
}

// ------------------- split-K GEMM, 64x64 tile, BK=16, 256 thr, 4x4 micro ------
// ADJ=true: A := adj + I, B rows pre-scaled by dinv[k]. (row scale dinv[i] applied in reduce)
// part layout: part[z][M][N]
template <bool ADJ>
__global__ void gemm_sk(const float* __restrict__ A, const float* __restrict__ B,
                        const float* __restrict__ dinv, float* __restrict__ part,
                        int M, int N, int lda, int kchunk) {
    __shared__ float As[16][68];
    __shared__ float Bs[16][68];
    const int row0 = blockIdx.y * 64;
    const int col0 = blockIdx.x * 64;
    const int kb   = blockIdx.z * kchunk;
    const int tid  = threadIdx.x;
    const int ty = tid >> 4, tx = tid & 15;
    const int ar  = tid >> 2;          // 0..63
    const int ac4 = (tid & 3) * 4;     // 0,4,8,12
    const int br  = tid >> 4;          // 0..15
    const int bc4 = (tid & 15) * 4;    // 0..60

    float acc[4][4] = {};
    for (int k0 = kb; k0 < kb + kchunk; k0 += 16) {
        float4 av = *(const float4*)&A[(row0 + ar) * lda + k0 + ac4];
        float4 bv = *(const float4*)&B[(k0 + br) * N + col0 + bc4];
        if (ADJ) {
            int d = (row0 + ar) - (k0 + ac4);
            if (d >= 0 && d < 4) ((float*)&av)[d] += 1.0f;   // + identity
            float s = dinv[k0 + br];
            bv.x *= s; bv.y *= s; bv.z *= s; bv.w *= s;
        }
        __syncthreads();
        As[ac4 + 0][ar] = av.x; As[ac4 + 1][ar] = av.y;
        As[ac4 + 2][ar] = av.z; As[ac4 + 3][ar] = av.w;
        *(float4*)&Bs[br][bc4] = bv;
        __syncthreads();
        #pragma unroll
        for (int k = 0; k < 16; k++) {
            float4 a4 = *(const float4*)&As[k][ty * 4];
            float4 b4 = *(const float4*)&Bs[k][tx * 4];
            float a[4] = {a4.x, a4.y, a4.z, a4.w};
            float b[4] = {b4.x, b4.y, b4.z, b4.w};
            #pragma unroll
            for (int m = 0; m < 4; m++)
                #pragma unroll
                for (int n = 0; n < 4; n++)
                    acc[m][n] = fmaf(a[m], b[n], acc[m][n]);
        }
    }
    float* dst = part + (size_t)blockIdx.z * M * N;
    #pragma unroll
    for (int m = 0; m < 4; m++) {
        int gr = row0 + ty * 4 + m;
        *(float4*)&dst[gr * N + col0 + tx * 4] =
            make_float4(acc[m][0], acc[m][1], acc[m][2], acc[m][3]);
    }
}

// ------------------- split-K reduce (+ optional dinv row scale + relu) --------
template <bool RELU, bool SCALE>
__global__ void reduce_k(const float* __restrict__ part, float* __restrict__ dst,
                         const float* __restrict__ dinv, int MN, int N, int splits) {
    int idx = (blockIdx.x * 256 + threadIdx.x) * 4;
    float4 v = *(const float4*)&part[idx];
    for (int s = 1; s < splits; s++) {
        float4 u = *(const float4*)&part[(size_t)s * MN + idx];
        v.x += u.x; v.y += u.y; v.z += u.z; v.w += u.w;
    }
    if (SCALE) {
        float sc = dinv[idx / N];
        v.x *= sc; v.y *= sc; v.z *= sc; v.w *= sc;
    }
    if (RELU) {
        v.x = fmaxf(v.x, 0.f); v.y = fmaxf(v.y, 0.f);
        v.z = fmaxf(v.z, 0.f); v.w = fmaxf(v.w, 0.f);
    }
    *(float4*)&dst[idx] = v;
}

// ------------------- pack [we1_p | we1_q] into 128x256 -------------------
__global__ void pack_kernel(const float* __restrict__ we1, float* __restrict__ bpack) {
    int idx = blockIdx.x * 256 + threadIdx.x;      // 32768
    int k = idx >> 8, n = idx & 255;
    bpack[idx] = (n < HH) ? we1[k * HH + n] : we1[(HH + k) * HH + (n - HH)];
}

// ------------------- c = t_emb @ we1[2H:] + be1 -------------------
__global__ void c_kernel(const float* __restrict__ time_emb, const int* __restrict__ t_ptr,
                         const float* __restrict__ we1, const float* __restrict__ be1,
                         float* __restrict__ cvec) {
    __shared__ float ps[8][HH];
    int h = threadIdx.x, kb = threadIdx.y;
    int t = t_ptr[0];
    const float* te = time_emb + t * HH;
    float s = 0.f;
    #pragma unroll
    for (int k = kb * 16; k < kb * 16 + 16; k++)
        s = fmaf(te[k], we1[(2 * HH + k) * HH + h], s);
    ps[kb][h] = s;
    __syncthreads();
    if (kb == 0) {
        float v = be1[h];
        #pragma unroll
        for (int u = 0; u < 8; u++) v += ps[u][h];
        cvec[h] = v;
    }
}

// ------------------- edge MLP + sigmoid -------------------
__global__ void edge_kernel(const float* __restrict__ pq, const float* __restrict__ cvec,
                            const float* __restrict__ we2, const float* __restrict__ be2,
                            float* __restrict__ sig) {
    __shared__ float Ps[32][68];
    __shared__ float Qs[32][68];
    __shared__ float Ws[32];
    const int i0 = blockIdx.y * 64;
    const int j0 = blockIdx.x * 64;
    const int tid = threadIdx.x;
    const int ty = tid >> 4, tx = tid & 15;

    float acc[4][4] = {};
    #pragma unroll
    for (int h0 = 0; h0 < HH; h0 += 32) {
        __syncthreads();
        #pragma unroll
        for (int l = tid; l < 64 * 8; l += 256) {
            int r = l >> 3, c4 = (l & 7) * 4;
            float4 pv = *(const float4*)&pq[(i0 + r) * 256 + h0 + c4];
            float4 qv = *(const float4*)&pq[(j0 + r) * 256 + HH + h0 + c4];
            float4 cv = *(const float4*)&cvec[h0 + c4];
            Ps[c4 + 0][r] = pv.x; Ps[c4 + 1][r] = pv.y;
            Ps[c4 + 2][r] = pv.z; Ps[c4 + 3][r] = pv.w;
            Qs[c4 + 0][r] = qv.x + cv.x; Qs[c4 + 1][r] = qv.y + cv.y;
            Qs[c4 + 2][r] = qv.z + cv.z; Qs[c4 + 3][r] = qv.w + cv.w;
        }
        if (tid < 32) Ws[tid] = we2[h0 + tid];
        __syncthreads();
        #pragma unroll
        for (int k = 0; k < 32; k++) {
            float w = Ws[k];
            float4 p4 = *(const float4*)&Ps[k][ty * 4];
            float4 q4 = *(const float4*)&Qs[k][tx * 4];
            float pv[4] = {p4.x, p4.y, p4.z, p4.w};
            float qv[4] = {q4.x, q4.y, q4.z, q4.w};
            #pragma unroll
            for (int m = 0; m < 4; m++)
                #pragma unroll
                for (int n = 0; n < 4; n++)
                    acc[m][n] = fmaf(fmaxf(pv[m] + qv[n], 0.f), w, acc[m][n]);
        }
    }
    float b = be2[0];
    #pragma unroll
    for (int m = 0; m < 4; m++) {
        int gi = i0 + ty * 4 + m;
        float4 o;
        float* ov = (float*)&o;
        #pragma unroll
        for (int n = 0; n < 4; n++)
            ov[n] = 1.0f / (1.0f + __expf(-(acc[m][n] + b)));
        *(float4*)&sig[gi * NN + j0 + tx * 4] = o;
    }
}

// ------------------- symmetrize (tiled transpose) -------------------
__global__ void sym_kernel(const float* __restrict__ sig, float* __restrict__ out) {
    __shared__ float t[32][33];
    const int r0 = blockIdx.y * 32;   // output row tile
    const int c0 = blockIdx.x * 32;   // output col tile
    const int tx = threadIdx.x, ty = threadIdx.y;
    #pragma unroll
    for (int u = 0; u < 4; u++) {
        int y = ty + 8 * u;
        t[y][tx] = sig[(c0 + y) * NN + r0 + tx];   // tile (c0, r0) coalesced
    }
    __syncthreads();
    #pragma unroll
    for (int u = 0; u < 4; u++) {
        int y = ty + 8 * u;
        float a = sig[(r0 + y) * NN + c0 + tx];
        out[(r0 + y) * NN + c0 + tx] = 0.5f * (a + t[tx][y]);
    }
}

// ------------------- launch -------------------
extern "C" void kernel_launch(void* const* d_in, const int* in_sizes, int n_in,
                              void* d_out, int out_size) {
    const float* x        = (const float*)d_in[0];   // 768x256
    const float* adj      = (const float*)d_in[1];   // 768x768
    const float* w1       = (const float*)d_in[2];   // 256x128
    const float* w2       = (const float*)d_in[3];   // 128x128
    const float* time_emb = (const float*)d_in[4];   // 100x128
    const float* we1      = (const float*)d_in[5];   // 384x128
    const float* be1      = (const float*)d_in[6];   // 128
    const float* we2      = (const float*)d_in[7];   // 128x1
    const float* be2      = (const float*)d_in[8];   // 1
    const int*   t_ptr    = (const int*)d_in[9];     // scalar
    float* out = (float*)d_out;

    float *dinv, *xw, *h1, *hw, *h2, *pq, *bpack, *cv, *sg, *part;
    cudaGetSymbolAddress((void**)&dinv,  g_dinv);
    cudaGetSymbolAddress((void**)&xw,    g_xw);
    cudaGetSymbolAddress((void**)&h1,    g_h1);
    cudaGetSymbolAddress((void**)&hw,    g_hw);
    cudaGetSymbolAddress((void**)&h2,    g_h2);
    cudaGetSymbolAddress((void**)&pq,    g_pq);
    cudaGetSymbolAddress((void**)&bpack, g_bpack);
    cudaGetSymbolAddress((void**)&cv,    g_c);
    cudaGetSymbolAddress((void**)&sg,    g_sig);
    cudaGetSymbolAddress((void**)&part,  g_part);

    const int MN = NN * HH;        // 98304
    const int MN2 = NN * 2 * HH;   // 196608

    dinv_kernel<<<NN / 8, 256>>>(adj, dinv);
    c_kernel<<<1, dim3(HH, 8)>>>(time_emb, t_ptr, we1, be1, cv);
    pack_kernel<<<HH * 2 * HH / 256, 256>>>(we1, bpack);

    // xw = x @ w1   (K=256, splits=4)
    gemm_sk<false><<<dim3(2, 12, 4), 256>>>(x, w1, nullptr, part, NN, HH, FDIM, 64);
    reduce_k<false, false><<<MN / 1024, 256>>>(part, xw, nullptr, MN, HH, 4);

    // h1 = relu(dinv_i * (adj+I) @ (dinv_k * xw))   (K=768, splits=6)
    gemm_sk<true><<<dim3(2, 12, 6), 256>>>(adj, xw, dinv, part, NN, HH, NN, 128);
    reduce_k<true, true><<<MN / 1024, 256>>>(part, h1, dinv, MN, HH, 6);

    // hw = h1 @ w2   (K=128, splits=4)
    gemm_sk<false><<<dim3(2, 12, 4), 256>>>(h1, w2, nullptr, part, NN, HH, HH, 32);
    reduce_k<false, false><<<MN / 1024, 256>>>(part, hw, nullptr, MN, HH, 4);

    // h2 = relu(Anorm @ hw)   (K=768, splits=6)
    gemm_sk<true><<<dim3(2, 12, 6), 256>>>(adj, hw, dinv, part, NN, HH, NN, 128);
    reduce_k<true, true><<<MN / 1024, 256>>>(part, h2, dinv, MN, HH, 6);

    // pq = h2 @ bpack   (N=256, K=128, splits=2)
    gemm_sk<false><<<dim3(4, 12, 2), 256>>>(h2, bpack, nullptr, part, NN, 2 * HH, HH, 64);
    reduce_k<false, false><<<MN2 / 1024, 256>>>(part, pq, nullptr, MN2, 2 * HH, 2);

    edge_kernel<<<dim3(NN / 64, NN / 64), 256>>>(pq, cv, we2, be2, sg);
    sym_kernel<<<dim3(NN / 32, NN / 32), dim3(32, 8)>>>(sg, out);
}

// round 3
// speedup vs baseline: 4.6960x; 1.1013x over previous
#include <cuda_runtime.h>
#include <cuda_bf16.h>

// GraphDenoiser: N=768, F=256, H=128 — fused split-K chain, no reduce kernels.
// Consumers sum producer's split-K slabs on operand load.

#define NN   768
#define FDIM 256
#define HH   128
#define MN   (NN * HH)        // 98304
#define MN2  (NN * 2 * HH)    // 196608

// ------------------- scratch -------------------
__device__ __align__(16) float g_dinv[NN];
__device__ __align__(16) float g_bpack[HH * 2 * HH];
__device__ __align__(16) float g_c[HH];
__device__ __align__(16) float g_sig[NN * NN];
__device__ __align__(16) float g_partA[6 * MN];    // >= 2*MN2
__device__ __align__(16) float g_partB[6 * MN];

// ------------------- prelude: dinv rows + c vector + we1 pack -------------------
__global__ void prelude_kernel(const float* __restrict__ adj,
                               const float* __restrict__ time_emb,
                               const int* __restrict__ t_ptr,
                               const float* __restrict__ we1,
                               const float* __restrict__ be1,
                               float* __restrict__ dinv,
                               float* __restrict__ cvec,
                               float* __restrict__ bpack) {
    int bid = blockIdx.x;
    int tid = threadIdx.x;
    if (bid < 96) {                       // dinv: 8 rows per block
        int row  = bid * 8 + (tid >> 5);
        int lane = tid & 31;
        const float4* r = (const float4*)(adj + row * NN);
        float s = 0.f;
        #pragma unroll
        for (int j = lane; j < NN / 4; j += 32) {
            float4 v = r[j];
            s += (v.x + v.y) + (v.z + v.w);
        }
        #pragma unroll
        for (int o = 16; o; o >>= 1) s += __shfl_xor_sync(0xffffffffu, s, o);
        s += 1.0f;
        if (lane == 0) dinv[row] = (s > 0.f) ? rsqrtf(s) : 0.f;
    } else if (bid == 96) {               // c = t_emb @ we1[2H:] + be1
        if (tid < HH) {
            int t = t_ptr[0];
            const float* te = time_emb + t * HH;
            float s = be1[tid];
            #pragma unroll 8
            for (int k = 0; k < HH; k++)
                s = fmaf(te[k], we1[(2 * HH + k) * HH + tid], s);
            cvec[tid] = s;
        }
    } else {                              // pack [we1_p | we1_q] -> 128x256
        int idx = (bid - 97) * 256 + tid;
        int k = idx >> 8, n = idx & 255;
        bpack[idx] = (n < HH) ? we1[k * HH + n] : we1[(HH + k) * HH + (n - HH)];
    }
}

// ------------------- generic fused GEMM -------------------
// 64x64 tile, BK=16, 512 threads, 2x4 micro, software pipelined.
// AMODE: 0 plain | 1 adj+I | 2 sum SA slabs * dinv[row], relu
// BMODE: 0 plain | 1 sum SB slabs * dinv[k]
// Writes partial slab z at dst + z*outslab.
template <int AMODE, int BMODE, int SA, int SB>
__global__ void __launch_bounds__(512, 2)
gemm_f(const float* __restrict__ A, const float* __restrict__ B,
       const float* __restrict__ dinv, float* __restrict__ dst,
       int N, int lda, int ldb, int kchunk, int outslab) {
    __shared__ float As[16][66];
    __shared__ float Bs[16][68];
    const int row0 = blockIdx.y * 64;
    const int col0 = blockIdx.x * 64;
    const int kb   = blockIdx.z * kchunk;
    const int tid  = threadIdx.x;
    const int ty = tid >> 4, tx = tid & 15;        // compute: 32 x 16
    const int ar = tid >> 3, ac2 = (tid & 7) * 2;  // A load: 64 x (8 float2)
    const int br = tid >> 5, bc2 = (tid & 31) * 2; // B load: 16 x (32 float2)

    auto loadA = [&](int k0) -> float2 {
        int gr = row0 + ar, gk = k0 + ac2;
        if (AMODE == 2) {
            float2 v = make_float2(0.f, 0.f);
            const float* base = A + gr * lda + gk;
            #pragma unroll
            for (int s = 0; s < SA; s++) {
                float2 u = *(const float2*)(base + s * MN);
                v.x += u.x; v.y += u.y;
            }
            float sc = dinv[gr];
            v.x = fmaxf(v.x * sc, 0.f);
            v.y = fmaxf(v.y * sc, 0.f);
            return v;
        } else {
            float2 v = *(const float2*)&A[gr * lda + gk];
            if (AMODE == 1) {
                if (gr == gk)     v.x += 1.0f;
                if (gr == gk + 1) v.y += 1.0f;
            }
            return v;
        }
    };
    auto loadB = [&](int k0) -> float2 {
        int gk = k0 + br, gc = col0 + bc2;
        if (BMODE == 1) {
            float2 v = make_float2(0.f, 0.f);
            const float* base = B + gk * ldb + gc;
            #pragma unroll
            for (int s = 0; s < SB; s++) {
                float2 u = *(const float2*)(base + s * MN);
                v.x += u.x; v.y += u.y;
            }
            float sc = dinv[gk];
            v.x *= sc; v.y *= sc;
            return v;
        } else {
            return *(const float2*)&B[gk * ldb + gc];
        }
    };

    float acc[2][4] = {};
    float2 a_reg = loadA(kb);
    float2 b_reg = loadB(kb);
    const int kend = kb + kchunk;
    for (int k0 = kb; k0 < kend; k0 += 16) {
        As[ac2 + 0][ar] = a_reg.x;
        As[ac2 + 1][ar] = a_reg.y;
        *(float2*)&Bs[br][bc2] = b_reg;
        __syncthreads();
        if (k0 + 16 < kend) {            // prefetch next tile (overlaps compute)
            a_reg = loadA(k0 + 16);
            b_reg = loadB(k0 + 16);
        }
        #pragma unroll
        for (int k = 0; k < 16; k++) {
            float a0 = As[k][ty * 2 + 0];
            float a1 = As[k][ty * 2 + 1];
            float4 b4 = *(const float4*)&Bs[k][tx * 4];
            float b[4] = {b4.x, b4.y, b4.z, b4.w};
            #pragma unroll
            for (int n = 0; n < 4; n++) {
                acc[0][n] = fmaf(a0, b[n], acc[0][n]);
                acc[1][n] = fmaf(a1, b[n], acc[1][n]);
            }
        }
        __syncthreads();
    }
    float* out = dst + (size_t)blockIdx.z * outslab;
    #pragma unroll
    for (int m = 0; m < 2; m++) {
        int gr = row0 + ty * 2 + m;
        *(float4*)&out[gr * N + col0 + tx * 4] =
            make_float4(acc[m][0], acc[m][1], acc[m][2], acc[m][3]);
    }
}

// ------------------- edge MLP + sigmoid -------------------
// 32x64 output tile, 256 threads, 2x4 micro; sums 2 pq slabs on load.
__global__ void __launch_bounds__(256, 2)
edge_kernel(const float* __restrict__ pq, const float* __restrict__ cvec,
            const float* __restrict__ we2, const float* __restrict__ be2,
            float* __restrict__ sig) {
    __shared__ float Ps[32][33];
    __shared__ float Qs[32][65];
    __shared__ float Ws[HH];
    __shared__ float Cs[HH];
    const int i0 = blockIdx.y * 32;
    const int j0 = blockIdx.x * 64;
    const int tid = threadIdx.x;
    const int ty = tid >> 4, tx = tid & 15;
    if (tid < HH) { Ws[tid] = we2[tid]; Cs[tid] = cvec[tid]; }

    float acc[2][4] = {};
    #pragma unroll
    for (int h0 = 0; h0 < HH; h0 += 32) {
        __syncthreads();
        {   // P: 32 rows x 32 h -> 256 thr x float4
            int r = tid >> 3, c4 = (tid & 7) * 4;
            const float* bp = pq + (i0 + r) * 256 + h0 + c4;
            float4 v0 = *(const float4*)bp;
            float4 v1 = *(const float4*)(bp + MN2);
            Ps[c4 + 0][r] = v0.x + v1.x;
            Ps[c4 + 1][r] = v0.y + v1.y;
            Ps[c4 + 2][r] = v0.z + v1.z;
            Ps[c4 + 3][r] = v0.w + v1.w;
        }
        #pragma unroll
        for (int l = tid; l < 64 * 8; l += 256) {  // Q: 64 rows x 32 h
            int r = l >> 3, c4 = (l & 7) * 4;
            const float* bq = pq + (j0 + r) * 256 + HH + h0 + c4;
            float4 v0 = *(const float4*)bq;
            float4 v1 = *(const float4*)(bq + MN2);
            Qs[c4 + 0][r] = v0.x + v1.x + Cs[h0 + c4 + 0];
            Qs[c4 + 1][r] = v0.y + v1.y + Cs[h0 + c4 + 1];
            Qs[c4 + 2][r] = v0.z + v1.z + Cs[h0 + c4 + 2];
            Qs[c4 + 3][r] = v0.w + v1.w + Cs[h0 + c4 + 3];
        }
        __syncthreads();
        #pragma unroll
        for (int k = 0; k < 32; k++) {
            float w = Ws[h0 + k];
            float p0 = Ps[k][ty * 2 + 0];
            float p1 = Ps[k][ty * 2 + 1];
            float qv[4];
            #pragma unroll
            for (int n = 0; n < 4; n++) qv[n] = Qs[k][tx * 4 + n];
            #pragma unroll
            for (int n = 0; n < 4; n++) {
                acc[0][n] = fmaf(fmaxf(p0 + qv[n], 0.f), w, acc[0][n]);
                acc[1][n] = fmaf(fmaxf(p1 + qv[n], 0.f), w, acc[1][n]);
            }
        }
    }
    float b = be2[0];
    #pragma unroll
    for (int m = 0; m < 2; m++) {
        int gi = i0 + ty * 2 + m;
        float4 o;
        float* ov = (float*)&o;
        #pragma unroll
        for (int n = 0; n < 4; n++)
            ov[n] = 1.0f / (1.0f + __expf(-(acc[m][n] + b)));
        *(float4*)&sig[gi * NN + j0 + tx * 4] = o;
    }
}

// ------------------- symmetrize (tiled transpose) -------------------
__global__ void sym_kernel(const float* __restrict__ sig, float* __restrict__ out) {
    __shared__ float t[32][33];
    const int r0 = blockIdx.y * 32;
    const int c0 = blockIdx.x * 32;
    const int tx = threadIdx.x, ty = threadIdx.y;
    #pragma unroll
    for (int u = 0; u < 4; u++) {
        int y = ty + 8 * u;
        t[y][tx] = sig[(c0 + y) * NN + r0 + tx];
    }
    __syncthreads();
    #pragma unroll
    for (int u = 0; u < 4; u++) {
        int y = ty + 8 * u;
        float a = sig[(r0 + y) * NN + c0 + tx];
        out[(r0 + y) * NN + c0 + tx] = 0.5f * (a + t[tx][y]);
    }
}

// ------------------- launch -------------------
extern "C" void kernel_launch(void* const* d_in, const int* in_sizes, int n_in,
                              void* d_out, int out_size) {
    const float* x        = (const float*)d_in[0];   // 768x256
    const float* adj      = (const float*)d_in[1];   // 768x768
    const float* w1       = (const float*)d_in[2];   // 256x128
    const float* w2       = (const float*)d_in[3];   // 128x128
    const float* time_emb = (const float*)d_in[4];   // 100x128
    const float* we1      = (const float*)d_in[5];   // 384x128
    const float* be1      = (const float*)d_in[6];   // 128
    const float* we2      = (const float*)d_in[7];   // 128x1
    const float* be2      = (const float*)d_in[8];   // 1
    const int*   t_ptr    = (const int*)d_in[9];     // scalar
    float* out = (float*)d_out;

    float *dinv, *bpack, *cv, *sg, *pA, *pB;
    cudaGetSymbolAddress((void**)&dinv,  g_dinv);
    cudaGetSymbolAddress((void**)&bpack, g_bpack);
    cudaGetSymbolAddress((void**)&cv,    g_c);
    cudaGetSymbolAddress((void**)&sg,    g_sig);
    cudaGetSymbolAddress((void**)&pA,    g_partA);
    cudaGetSymbolAddress((void**)&pB,    g_partB);

    prelude_kernel<<<225, 256>>>(adj, time_emb, t_ptr, we1, be1, dinv, cv, bpack);

    // xw partials (4 slabs) -> pA          [x(768x256) @ w1(256x128)]
    gemm_f<0, 0, 1, 1><<<dim3(2, 12, 4), 512>>>(x, w1, dinv, pA, HH, FDIM, HH, 64, MN);
    // (adj+I) @ (dinv_k * sum4 pA) -> pB (6 slabs)
    gemm_f<1, 1, 1, 4><<<dim3(2, 12, 6), 512>>>(adj, pA, dinv, pB, HH, NN, HH, 128, MN);
    // h1 = relu(dinv_i * sum6 pB); hw partials = h1 @ w2 -> pA (4 slabs)
    gemm_f<2, 0, 6, 1><<<dim3(2, 12, 4), 512>>>(pB, w2, dinv, pA, HH, HH, HH, 32, MN);
    // (adj+I) @ (dinv_k * sum4 pA) -> pB (6 slabs)
    gemm_f<1, 1, 1, 4><<<dim3(2, 12, 6), 512>>>(adj, pA, dinv, pB, HH, NN, HH, 128, MN);
    // h2 = relu(dinv_i * sum6 pB); pq partials = h2 @ bpack -> pA (2 slabs, N=256)
    gemm_f<2, 0, 6, 1><<<dim3(4, 12, 2), 512>>>(pB, bpack, dinv, pA, 2 * HH, HH, 2 * HH, 64, MN2);

    edge_kernel<<<dim3(NN / 64, NN / 32), 256>>>(pA, cv, we2, be2, sg);
    sym_kernel<<<dim3(NN / 32, NN / 32), dim3(32, 8)>>>(sg, out);
}

// round 6
// speedup vs baseline: 5.7312x; 1.2204x over previous
#include <cuda_runtime.h>

// GraphDenoiser N=768, F=256, H=128 — multi-launch, split-K everywhere,
// double-buffered GEMM tiles, f32x2-packed edge MLP.

#define NN   768
#define FDIM 256
#define HH   128
#define MN   (NN * HH)       // 98304
#define MN2  (NN * 2 * HH)   // 196608

// ------------------- scratch -------------------
__device__ __align__(16) float g_dinv[NN];
__device__ __align__(16) float g_bpack[HH * 2 * HH];
__device__ __align__(16) float g_c[HH];
__device__ __align__(16) float g_xwf[MN];       // reduced xw, then reduced hw
__device__ __align__(16) float g_pqf[MN2];
__device__ __align__(16) float g_sig[NN * NN];
__device__ __align__(16) float g_S1[12 * MN];   // adj-gemm slabs
__device__ __align__(16) float g_S2[8 * MN];    // xw/hw slabs; pq slabs (4*MN2)

// ------------------- f32x2 helpers -------------------
__device__ __forceinline__ unsigned long long pk2(float lo, float hi) {
    unsigned long long d;
    asm("mov.b64 %0, {%1, %2};" : "=l"(d) : "f"(lo), "f"(hi));
    return d;
}
__device__ __forceinline__ float2 upk2(unsigned long long d) {
    float2 v;
    asm("mov.b64 {%0, %1}, %2;" : "=f"(v.x), "=f"(v.y) : "l"(d));
    return v;
}
#define F32X2_ADD(d, a, b) \
    asm("add.rn.f32x2 %0, %1, %2;" : "=l"(d) : "l"(a), "l"(b))
#define F32X2_FMA(d, a, b, c) \
    asm("fma.rn.f32x2 %0, %1, %2, %3;" : "=l"(d) : "l"(a), "l"(b), "l"(c))

// ------------------- GEMM tile: 64 rows x 128 cols, BK=16, double-buffered ---
// AMODE: 0 plain | 1 adj+I | 2 relu(dinv[row] * sum of SA slabs)
#define SMA_STRIDE 68
#define SMB_STRIDE 132
template<int AMODE, int SA>
__device__ __forceinline__ void gemm_tile(
    const float* __restrict__ A, const float* __restrict__ B,
    const float* __restrict__ dinv, float* __restrict__ out, float* sm,
    int row0, int bcol0, int ocol0, int kb, int nsteps,
    int lda, int ldb, int ldo)
{
    float* smA = sm;                       // [2][16][68]
    float* smB = sm + 2 * 16 * SMA_STRIDE; // [2][16][132]
    const int tid = threadIdx.x;
    const int ty = tid >> 5, tx = tid & 31;
    const int ar = tid >> 3, ac2 = (tid & 7) * 2;
    const int br = tid >> 5, bc4 = (tid & 31) * 4;
    const int gr = row0 + ar;

    auto ldA = [&](int k0) -> float2 {
        int gk = k0 + ac2;
        if (AMODE == 2) {
            float2 v = make_float2(0.f, 0.f);
            const float* base = A + gr * lda + gk;
            #pragma unroll
            for (int s = 0; s < SA; s++) {
                float2 u = *(const float2*)(base + s * MN);
                v.x += u.x; v.y += u.y;
            }
            float sc = dinv[gr];
            v.x = fmaxf(v.x * sc, 0.f);
            v.y = fmaxf(v.y * sc, 0.f);
            return v;
        } else {
            float2 v = *(const float2*)&A[gr * lda + gk];
            if (AMODE == 1) {
                if (gr == gk)          v.x += 1.0f;
                else if (gr == gk + 1) v.y += 1.0f;
            }
            return v;
        }
    };
    auto ldB = [&](int k0) -> float4 {
        return *(const float4*)&B[(k0 + br) * ldb + bcol0 + bc4];
    };

    float acc[4][4] = {};
    float2 a_reg = ldA(kb);
    float4 b_reg = ldB(kb);
    int buf = 0;
    smA[(ac2 + 0) * SMA_STRIDE + ar] = a_reg.x;
    smA[(ac2 + 1) * SMA_STRIDE + ar] = a_reg.y;
    *(float4*)&smB[br * SMB_STRIDE + bc4] = b_reg;
    __syncthreads();

    for (int s = 0; s < nsteps; s++) {
        float2 a_nxt; float4 b_nxt;
        bool more = (s + 1 < nsteps);
        if (more) {
            a_nxt = ldA(kb + (s + 1) * 16);
            b_nxt = ldB(kb + (s + 1) * 16);
        }
        const float* cA = smA + buf * 16 * SMA_STRIDE;
        const float* cB = smB + buf * 16 * SMB_STRIDE;
        #pragma unroll
        for (int k = 0; k < 16; k++) {
            float4 a4 = *(const float4*)&cA[k * SMA_STRIDE + ty * 4];
            float4 b4 = *(const float4*)&cB[k * SMB_STRIDE + tx * 4];
            float a[4] = {a4.x, a4.y, a4.z, a4.w};
            float b[4] = {b4.x, b4.y, b4.z, b4.w};
            #pragma unroll
            for (int m = 0; m < 4; m++)
                #pragma unroll
                for (int n = 0; n < 4; n++)
                    acc[m][n] = fmaf(a[m], b[n], acc[m][n]);
        }
        if (more) {
            buf ^= 1;
            float* nA = smA + buf * 16 * SMA_STRIDE;
            float* nB = smB + buf * 16 * SMB_STRIDE;
            nA[(ac2 + 0) * SMA_STRIDE + ar] = a_nxt.x;
            nA[(ac2 + 1) * SMA_STRIDE + ar] = a_nxt.y;
            *(float4*)&nB[br * SMB_STRIDE + bc4] = b_nxt;
            __syncthreads();
        }
    }
    #pragma unroll
    for (int m = 0; m < 4; m++) {
        int orow = row0 + ty * 4 + m;
        *(float4*)&out[orow * ldo + ocol0 + tx * 4] =
            make_float4(acc[m][0], acc[m][1], acc[m][2], acc[m][3]);
    }
}

// ------------------- K1: prelude + xw slabs -------------------
__global__ void __launch_bounds__(512)
k_prelude_xw(const float* __restrict__ x, const float* __restrict__ w1,
             const float* __restrict__ adj, const float* __restrict__ time_emb,
             const int* __restrict__ t_ptr, const float* __restrict__ we1,
             const float* __restrict__ be1)
{
    __shared__ __align__(16) float sm[6400];
    const int b = blockIdx.x;
    const int tid = threadIdx.x;
    if (b < 96) {
        int row = b % 12, z = b / 12;          // z 0..7, kchunk 32
        gemm_tile<0, 1>(x, w1, nullptr, g_S2 + z * MN, sm,
                        row * 64, 0, 0, z * 32, 2, FDIM, HH, HH);
    } else {
        int rb = b - 96;                        // 0..47
        {   // dinv: 16 warps per block, 48 blocks => 768 rows
            int row  = rb * 16 + (tid >> 5);
            int lane = tid & 31;
            const float4* r = (const float4*)(adj + row * NN);
            float s = 0.f;
            #pragma unroll
            for (int j = lane; j < NN / 4; j += 32) {
                float4 v = r[j];
                s += (v.x + v.y) + (v.z + v.w);
            }
            #pragma unroll
            for (int o = 16; o; o >>= 1) s += __shfl_xor_sync(0xffffffffu, s, o);
            s += 1.0f;
            if (lane == 0) g_dinv[row] = (s > 0.f) ? rsqrtf(s) : 0.f;
        }
        for (int idx = rb * 512 + tid; idx < HH * 2 * HH; idx += 48 * 512) {
            int k = idx >> 8, n = idx & 255;
            g_bpack[idx] = (n < HH) ? we1[k * HH + n] : we1[(HH + k) * HH + (n - HH)];
        }
        if (rb == 47 && tid < HH) {
            int t = t_ptr[0];
            const float* te = time_emb + t * HH;
            float s = be1[tid];
            #pragma unroll 8
            for (int k = 0; k < HH; k++)
                s = fmaf(te[k], we1[(2 * HH + k) * HH + tid], s);
            g_c[tid] = s;
        }
    }
}

// ------------------- reduce 8 slabs * dinv[row] -------------------
__global__ void __launch_bounds__(256)
k_reduce8(const float* __restrict__ src, float* __restrict__ dst) {
    int idx4 = (blockIdx.x * 256 + threadIdx.x) * 4;   // 96*256*4 = MN
    float4 v = *(const float4*)&src[idx4];
    #pragma unroll
    for (int s = 1; s < 8; s++) {
        float4 u = *(const float4*)&src[s * MN + idx4];
        v.x += u.x; v.y += u.y; v.z += u.z; v.w += u.w;
    }
    float sc = g_dinv[idx4 >> 7];
    v.x *= sc; v.y *= sc; v.z *= sc; v.w *= sc;
    *(float4*)&dst[idx4] = v;
}

// ------------------- adj GEMM slabs: (adj+I) @ B -> S1 (z=12) -------------------
__global__ void __launch_bounds__(512)
k_adj(const float* __restrict__ adj, const float* __restrict__ Bm) {
    __shared__ __align__(16) float sm[6400];
    int row = blockIdx.x % 12, z = blockIdx.x / 12;    // z 0..11, kchunk 64
    gemm_tile<1, 1>(adj, Bm, nullptr, g_S1 + z * MN, sm,
                    row * 64, 0, 0, z * 64, 4, NN, HH, HH);
}

// ------------------- hw slabs: relu(dinv*sum12 S1) @ w2 -> S2 (z=8) ---------
__global__ void __launch_bounds__(512)
k_hw(const float* __restrict__ w2) {
    __shared__ __align__(16) float sm[6400];
    int row = blockIdx.x % 12, z = blockIdx.x / 12;    // z 0..7, kchunk 16
    gemm_tile<2, 12>(g_S1, w2, g_dinv, g_S2 + z * MN, sm,
                     row * 64, 0, 0, z * 16, 1, HH, HH, HH);
}

// ------------------- pq slabs: relu(dinv*sum12 S1) @ bpack -> S2 (4xMN2) ----
__global__ void __launch_bounds__(512)
k_pq() {
    __shared__ __align__(16) float sm[6400];
    int row = blockIdx.x % 12, rem = blockIdx.x / 12;  // rem 0..7
    int col = rem & 1, z = rem >> 1;                   // z 0..3, kchunk 32
    gemm_tile<2, 12>(g_S1, g_bpack, g_dinv, g_S2 + z * MN2, sm,
                     row * 64, col * 128, col * 128, z * 32, 2, HH, 2 * HH, 2 * HH);
}

// ------------------- reduce 4 pq slabs + c on q half -------------------
__global__ void __launch_bounds__(512)
k_reduce4c() {
    int idx4 = (blockIdx.x * 512 + threadIdx.x) * 4;   // 96*512*4 = MN2
    float4 v = *(const float4*)&g_S2[idx4];
    #pragma unroll
    for (int s = 1; s < 4; s++) {
        float4 u = *(const float4*)&g_S2[s * MN2 + idx4];
        v.x += u.x; v.y += u.y; v.z += u.z; v.w += u.w;
    }
    int col = idx4 & 255;
    if (col >= HH) {
        float4 c = *(const float4*)&g_c[col - HH];
        v.x += c.x; v.y += c.y; v.z += c.z; v.w += c.w;
    }
    *(float4*)&g_pqf[idx4] = v;
}

// ------------------- edge MLP + sigmoid (f32x2 packed rows) -------------------
// 64x64 tile per block, 512 threads, 8 out/thread = 4 rows (2 packed pairs) x 2 cols.
__global__ void __launch_bounds__(512)
k_edge(const float* __restrict__ we2, const float* __restrict__ be2) {
    __shared__ __align__(16) float Ps[32 * 68];
    __shared__ __align__(8)  float Qs[32 * 66];
    __shared__ float Ws[HH];
    const int i0 = (blockIdx.x / 12) * 64;
    const int j0 = (blockIdx.x % 12) * 64;
    const int tid = threadIdx.x;
    const int ty = tid >> 5, tx = tid & 31;     // rows ty*4.., cols tx*2..
    const int lr = tid >> 3, lc4 = (tid & 7) * 4;
    if (tid < HH) Ws[tid] = we2[tid];

    unsigned long long acc2[2][2] = {};          // [row-pair][col]
    #pragma unroll
    for (int h0 = 0; h0 < HH; h0 += 32) {
        __syncthreads();
        float4 pv = *(const float4*)&g_pqf[(i0 + lr) * 256 + h0 + lc4];
        float4 qv = *(const float4*)&g_pqf[(j0 + lr) * 256 + HH + h0 + lc4];
        Ps[(lc4 + 0) * 68 + lr] = pv.x;
        Ps[(lc4 + 1) * 68 + lr] = pv.y;
        Ps[(lc4 + 2) * 68 + lr] = pv.z;
        Ps[(lc4 + 3) * 68 + lr] = pv.w;
        Qs[(lc4 + 0) * 66 + lr] = qv.x;
        Qs[(lc4 + 1) * 66 + lr] = qv.y;
        Qs[(lc4 + 2) * 66 + lr] = qv.z;
        Qs[(lc4 + 3) * 66 + lr] = qv.w;
        __syncthreads();
        #pragma unroll
        for (int k = 0; k < 32; k++) {
            float w = Ws[h0 + k];
            unsigned long long w2 = pk2(w, w);
            float4 p4 = *(const float4*)&Ps[k * 68 + ty * 4];   // 4 rows
            float2 q2 = *(const float2*)&Qs[k * 66 + tx * 2];   // 2 cols
            unsigned long long pp[2] = { pk2(p4.x, p4.y), pk2(p4.z, p4.w) };
            unsigned long long qd[2] = { pk2(q2.x, q2.x), pk2(q2.y, q2.y) };
            #pragma unroll
            for (int mp = 0; mp < 2; mp++) {
                #pragma unroll
                for (int n = 0; n < 2; n++) {
                    unsigned long long sum;
                    F32X2_ADD(sum, pp[mp], qd[n]);
                    float2 sv = upk2(sum);
                    sv.x = fmaxf(sv.x, 0.f);
                    sv.y = fmaxf(sv.y, 0.f);
                    unsigned long long rv = pk2(sv.x, sv.y);
                    F32X2_FMA(acc2[mp][n], rv, w2, acc2[mp][n]);
                }
            }
        }
    }
    float bb = be2[0];
    #pragma unroll
    for (int mp = 0; mp < 2; mp++) {
        float2 c0 = upk2(acc2[mp][0]);   // col tx*2,   rows (2mp, 2mp+1)
        float2 c1 = upk2(acc2[mp][1]);   // col tx*2+1
        float2 o0, o1;
        o0.x = 1.0f / (1.0f + __expf(-(c0.x + bb)));
        o0.y = 1.0f / (1.0f + __expf(-(c1.x + bb)));
        o1.x = 1.0f / (1.0f + __expf(-(c0.y + bb)));
        o1.y = 1.0f / (1.0f + __expf(-(c1.y + bb)));
        *(float2*)&g_sig[(i0 + ty * 4 + mp * 2 + 0) * NN + j0 + tx * 2] = o0;
        *(float2*)&g_sig[(i0 + ty * 4 + mp * 2 + 1) * NN + j0 + tx * 2] = o1;
    }
}

// ------------------- symmetrize -------------------
__global__ void __launch_bounds__(512)
k_sym(float* __restrict__ out) {
    __shared__ __align__(16) float T[64 * 65];
    const int r0 = (blockIdx.x / 12) * 64;
    const int c0 = (blockIdx.x % 12) * 64;
    const int tid = threadIdx.x;
    int row = tid >> 3, c8 = (tid & 7) * 8;
    float4 v0 = *(const float4*)&g_sig[(c0 + row) * NN + r0 + c8];
    float4 v1 = *(const float4*)&g_sig[(c0 + row) * NN + r0 + c8 + 4];
    T[row * 65 + c8 + 0] = v0.x; T[row * 65 + c8 + 1] = v0.y;
    T[row * 65 + c8 + 2] = v0.z; T[row * 65 + c8 + 3] = v0.w;
    T[row * 65 + c8 + 4] = v1.x; T[row * 65 + c8 + 5] = v1.y;
    T[row * 65 + c8 + 6] = v1.z; T[row * 65 + c8 + 7] = v1.w;
    __syncthreads();
    float4 a0 = *(const float4*)&g_sig[(r0 + row) * NN + c0 + c8];
    float4 a1 = *(const float4*)&g_sig[(r0 + row) * NN + c0 + c8 + 4];
    float o[8] = {a0.x, a0.y, a0.z, a0.w, a1.x, a1.y, a1.z, a1.w};
    #pragma unroll
    for (int i = 0; i < 8; i++)
        o[i] = 0.5f * (o[i] + T[(c8 + i) * 65 + row]);
    *(float4*)&out[(r0 + row) * NN + c0 + c8]     = make_float4(o[0], o[1], o[2], o[3]);
    *(float4*)&out[(r0 + row) * NN + c0 + c8 + 4] = make_float4(o[4], o[5], o[6], o[7]);
}

// ------------------- launch -------------------
extern "C" void kernel_launch(void* const* d_in, const int* in_sizes, int n_in,
                              void* d_out, int out_size) {
    const float* x        = (const float*)d_in[0];
    const float* adj      = (const float*)d_in[1];
    const float* w1       = (const float*)d_in[2];
    const float* w2       = (const float*)d_in[3];
    const float* time_emb = (const float*)d_in[4];
    const float* we1      = (const float*)d_in[5];
    const float* be1      = (const float*)d_in[6];
    const float* we2      = (const float*)d_in[7];
    const float* be2      = (const float*)d_in[8];
    const int*   t_ptr    = (const int*)d_in[9];
    float* out = (float*)d_out;

    float *xwf, *S2;
    cudaGetSymbolAddress((void**)&xwf, g_xwf);
    cudaGetSymbolAddress((void**)&S2,  g_S2);

    k_prelude_xw<<<144, 512>>>(x, w1, adj, time_emb, t_ptr, we1, be1);
    k_reduce8<<<96, 256>>>(S2, xwf);          // xwf = dinv_k * sum8(xw slabs)
    k_adj<<<144, 512>>>(adj, xwf);            // S1 = (adj+I) @ xwf   (12 slabs)
    k_hw<<<96, 512>>>(w2);                    // S2 = h1 @ w2         (8 slabs)
    k_reduce8<<<96, 256>>>(S2, xwf);          // xwf = dinv_k * sum8(hw slabs)
    k_adj<<<144, 512>>>(adj, xwf);            // S1 = (adj+I) @ xwf   (12 slabs)
    k_pq<<<96, 512>>>();                      // S2 = h2 @ bpack      (4 slabs, N=256)
    k_reduce4c<<<96, 512>>>();                // pqf = sum4 + c
    k_edge<<<144, 512>>>(we2, be2);           // sig
    k_sym<<<144, 512>>>(out);                 // out = (sig+sig^T)/2
}